// round 2
// baseline (speedup 1.0000x reference)
#include <cuda_runtime.h>
#include <cstdint>

#define BB 512
#define LL 2048
#define CC 32

// Device scratch (no allocation allowed)
__device__ double g_logz[BB];
__device__ double g_score[BB];

// ---------- packed f32x2 helpers (sm_103a; ptxas never emits FFMA2 from C++) ----------
__device__ __forceinline__ unsigned long long pack2(float lo, float hi) {
    unsigned long long r;
    asm("mov.b64 %0, {%1, %2};" : "=l"(r) : "f"(lo), "f"(hi));
    return r;
}
__device__ __forceinline__ unsigned long long mul2(unsigned long long a, unsigned long long b) {
    unsigned long long r;
    asm("mul.rn.f32x2 %0, %1, %2;" : "=l"(r) : "l"(a), "l"(b));
    return r;
}
__device__ __forceinline__ void fma2(unsigned long long& c, unsigned long long a, unsigned long long b) {
    asm("fma.rn.f32x2 %0, %1, %2, %0;" : "+l"(c) : "l"(a), "l"(b));
}
__device__ __forceinline__ unsigned long long add2(unsigned long long a, unsigned long long b) {
    unsigned long long r;
    asm("add.rn.f32x2 %0, %1, %2;" : "=l"(r) : "l"(a), "l"(b));
    return r;
}
__device__ __forceinline__ float rcp_approx(float x) {
    float r; asm("rcp.approx.f32 %0, %1;" : "=f"(r) : "f"(x)); return r;
}

// One recursion step. Reads sv[PAR_], writes sv[PAR_^1].
// v_new_i = (sum_j v_j * expT[i][j]) * exp(emit_i) / v[0] ;  M += log(v[0])
#define STEP(PAR_, EV_) do {                                                  \
    __syncthreads();                                                          \
    const ulonglong2* pv_ = (const ulonglong2*)(sv[(PAR_)]);                  \
    ulonglong2 q0_ = pv_[0], q1_ = pv_[1], q2_ = pv_[2], q3_ = pv_[3];        \
    ulonglong2 q4_ = pv_[4], q5_ = pv_[5], q6_ = pv_[6], q7_ = pv_[7];        \
    float v0_, vh_;                                                           \
    asm("mov.b64 {%0, %1}, %2;" : "=f"(v0_), "=f"(vh_) : "l"(q0_.x));         \
    (void)vh_;                                                                \
    float r_  = rcp_approx(v0_);                                              \
    float ee_ = __expf(EV_) * r_;                                             \
    unsigned long long a0_ = mul2(q0_.x, tp[0]);                              \
    unsigned long long a1_ = mul2(q0_.y, tp[1]);                              \
    unsigned long long a2_ = mul2(q1_.x, tp[2]);                              \
    unsigned long long a3_ = mul2(q1_.y, tp[3]);                              \
    fma2(a0_, q2_.x, tp[4]);  fma2(a1_, q2_.y, tp[5]);                        \
    fma2(a2_, q3_.x, tp[6]);  fma2(a3_, q3_.y, tp[7]);                        \
    fma2(a0_, q4_.x, tp[8]);  fma2(a1_, q4_.y, tp[9]);                        \
    fma2(a2_, q5_.x, tp[10]); fma2(a3_, q5_.y, tp[11]);                       \
    fma2(a0_, q6_.x, tp[12]); fma2(a1_, q6_.y, tp[13]);                       \
    fma2(a2_, q7_.x, tp[14]); fma2(a3_, q7_.y, tp[15]);                       \
    unsigned long long s0_ = add2(a0_, a1_);                                  \
    unsigned long long s1_ = add2(a2_, a3_);                                  \
    unsigned long long s__ = add2(s0_, s1_);                                  \
    float sl_, sh_;                                                           \
    asm("mov.b64 {%0, %1}, %2;" : "=f"(sl_), "=f"(sh_) : "l"(s__));           \
    float vn_ = (sl_ + sh_) * ee_;                                            \
    sv[(PAR_) ^ 1][lane] = vn_;                                               \
    M += (double)__logf(v0_);                                                 \
} while (0)

// Blocks 0..BB-1: forward recursion (1 warp = 1 batch, lane = state).
// Blocks BB..2*BB-1: path score for batch (blockIdx.x - BB).
__global__ void __launch_bounds__(CC) crf_main(
    const float* __restrict__ emissions,
    const float* __restrict__ transitions,
    const int*   __restrict__ tags,
    const int*   __restrict__ mask)
{
    __shared__ __align__(16) float sv[2][CC];
    const int lane = threadIdx.x;

    if (blockIdx.x < BB) {
        // ---------------- forward recursion ----------------
        const int b = blockIdx.x;

        // expT row for this lane (state i), packed into 16 f32x2 registers
        unsigned long long tp[16];
#pragma unroll
        for (int k = 0; k < 16; ++k) {
            float a = __expf(transitions[lane * CC + 2 * k]);
            float c = __expf(transitions[lane * CC + 2 * k + 1]);
            tp[k] = pack2(a, c);
        }

        const float* em = emissions + (size_t)b * (LL * CC) + lane;

        // v = exp(alpha0), stored in sv[1]; step t reads sv[t&1]
        sv[1][lane] = __expf(em[0]);
        double M = 0.0;

        // 8-deep register prefetch of emission rows (coalesced 128B/warp/step)
        float ebuf[8];
#pragma unroll
        for (int k = 0; k < 8; ++k) ebuf[k] = em[(1 + k) * CC];

        int t = 1;
#pragma unroll 1
        for (int blk = 0; blk < 255; ++blk) {   // t = 1 .. 2040
#pragma unroll
            for (int k = 0; k < 8; ++k) {
                float ev = ebuf[k];
                int tpre = t + 8;
                if (tpre <= LL - 1) ebuf[k] = em[tpre * CC];
                STEP((1 + k) & 1, ev);          // parity of t (blk*8 even)
                ++t;
            }
        }
#pragma unroll
        for (int k = 0; k < 7; ++k) {           // t = 2041 .. 2047
            STEP((1 + k) & 1, ebuf[k]);
            ++t;
        }

        // log_Z = M + log(sum_i v_i); final v is in sv[0] (t=2047 wrote sv[0])
        __syncthreads();
        float tot = sv[0][lane];
#pragma unroll
        for (int o = 16; o; o >>= 1) tot += __shfl_xor_sync(0xffffffffu, tot, o);
        if (lane == 0) g_logz[b] = M + (double)logf(tot);
    } else {
        // ---------------- path score ----------------
        const int b = blockIdx.x - BB;
        const int* tg = tags + (size_t)b * LL;
        const int* mk = mask + (size_t)b * LL;
        const float* eb = emissions + (size_t)b * (LL * CC);

        int ms = 0;
        for (int t = lane; t < LL; t += 32) ms += mk[t];
#pragma unroll
        for (int o = 16; o; o >>= 1) ms += __shfl_xor_sync(0xffffffffu, ms, o);

        double acc = 0.0;
        for (int t = lane; t < LL - 1; t += 32) {
            int a = tg[t], c = tg[t + 1];
            float m0 = (float)mk[t], m1 = (float)mk[t + 1];
            acc += (double)(eb[t * CC + a] * m0)
                 + (double)(transitions[a * CC + c] * m1);
        }
#pragma unroll
        for (int o = 16; o; o >>= 1) acc += __shfl_xor_sync(0xffffffffu, acc, o);

        if (lane == 0) {
            int last_idx = ms - 1; if (last_idx < 0) last_idx = 0;
            int msc = ms; if (msc < 1) msc = 1;
            int le_t = msc - 1;
            int last_tag = tg[last_idx];
            acc += (double)eb[le_t * CC + last_tag];
            g_score[b] = acc;
        }
    }
}

__global__ void crf_final(float* __restrict__ out) {
    __shared__ double s[BB];
    int tid = threadIdx.x;
    s[tid] = g_logz[tid] - g_score[tid];
    __syncthreads();
#pragma unroll
    for (int st = BB / 2; st > 0; st >>= 1) {
        if (tid < st) s[tid] += s[tid + st];
        __syncthreads();
    }
    if (tid == 0) out[0] = (float)(s[0] / (double)BB);
}

extern "C" void kernel_launch(void* const* d_in, const int* in_sizes, int n_in,
                              void* d_out, int out_size) {
    const float* emissions   = (const float*)d_in[0];
    const float* transitions = (const float*)d_in[1];
    const int*   tags        = (const int*)d_in[2];
    const int*   mask        = (const int*)d_in[3];
    (void)in_sizes; (void)n_in; (void)out_size;

    crf_main<<<2 * BB, CC>>>(emissions, transitions, tags, mask);
    crf_final<<<1, BB>>>((float*)d_out);
}

// round 3
// speedup vs baseline: 1.2321x; 1.2321x over previous
#include <cuda_runtime.h>
#include <cstdint>

#define BB 512
#define LL 2048
#define CC 32

// Device scratch (no allocation allowed)
__device__ double g_logz[BB];
__device__ double g_score[BB];
__device__ int    g_ticket;

// ---------- packed f32x2 helpers (sm_103a; ptxas never emits FFMA2 from C++) ----------
__device__ __forceinline__ unsigned long long mul2(unsigned long long a, unsigned long long b) {
    unsigned long long r;
    asm("mul.rn.f32x2 %0, %1, %2;" : "=l"(r) : "l"(a), "l"(b));
    return r;
}
__device__ __forceinline__ void fma2(unsigned long long& c, unsigned long long a, unsigned long long b) {
    asm("fma.rn.f32x2 %0, %1, %2, %0;" : "+l"(c) : "l"(a), "l"(b));
}
__device__ __forceinline__ unsigned long long add2(unsigned long long a, unsigned long long b) {
    unsigned long long r;
    asm("add.rn.f32x2 %0, %1, %2;" : "=l"(r) : "l"(a), "l"(b));
    return r;
}
__device__ __forceinline__ float rcp_approx(float x) {
    float r; asm("rcp.approx.f32 %0, %1;" : "=f"(r) : "f"(x)); return r;
}

// One recursion step. Reads sv[PAR_], writes sv[PAR_^1].
// RN_ = renormalize this step by v[0] (exact bookkeeping: Ml2 += log2(v0)).
// All fp32; no fp64 anywhere in the loop.
#define STEP(PAR_, EV_, RN_) do {                                             \
    __syncthreads();                                                          \
    const ulonglong2* pv_ = (const ulonglong2*)(sv[(PAR_)]);                  \
    ulonglong2 q0_ = pv_[0], q1_ = pv_[1], q2_ = pv_[2], q3_ = pv_[3];        \
    ulonglong2 q4_ = pv_[4], q5_ = pv_[5], q6_ = pv_[6], q7_ = pv_[7];        \
    float ee_;                                                                \
    if (RN_) {                                                                \
        float v0_, vh_;                                                       \
        asm("mov.b64 {%0, %1}, %2;" : "=f"(v0_), "=f"(vh_) : "l"(q0_.x));     \
        (void)vh_;                                                            \
        ee_ = __expf(EV_) * rcp_approx(v0_);                                  \
        Ml2 += __log2f(v0_);                                                  \
    } else {                                                                  \
        ee_ = __expf(EV_);                                                    \
    }                                                                         \
    unsigned long long a0_ = mul2(q0_.x, tp[0]);                              \
    unsigned long long a1_ = mul2(q0_.y, tp[1]);                              \
    unsigned long long a2_ = mul2(q1_.x, tp[2]);                              \
    unsigned long long a3_ = mul2(q1_.y, tp[3]);                              \
    fma2(a0_, q2_.x, tp[4]);  fma2(a1_, q2_.y, tp[5]);                        \
    fma2(a2_, q3_.x, tp[6]);  fma2(a3_, q3_.y, tp[7]);                        \
    fma2(a0_, q4_.x, tp[8]);  fma2(a1_, q4_.y, tp[9]);                        \
    fma2(a2_, q5_.x, tp[10]); fma2(a3_, q5_.y, tp[11]);                       \
    fma2(a0_, q6_.x, tp[12]); fma2(a1_, q6_.y, tp[13]);                       \
    fma2(a2_, q7_.x, tp[14]); fma2(a3_, q7_.y, tp[15]);                       \
    unsigned long long s0_ = add2(a0_, a1_);                                  \
    unsigned long long s1_ = add2(a2_, a3_);                                  \
    unsigned long long s__ = add2(s0_, s1_);                                  \
    float sl_, sh_;                                                           \
    asm("mov.b64 {%0, %1}, %2;" : "=f"(sl_), "=f"(sh_) : "l"(s__));           \
    sv[(PAR_) ^ 1][lane] = (sl_ + sh_) * ee_;                                 \
} while (0)

__global__ void crf_init() {
    if (threadIdx.x == 0) g_ticket = 0;
}

// Blocks 0..BB-1: forward recursion (1 warp = 1 batch, lane = state).
// Blocks BB..2*BB-1: path score for batch (blockIdx.x - BB).
// Last block to finish (ticket) reduces and writes the scalar output.
__global__ void __launch_bounds__(CC) crf_main(
    const float* __restrict__ emissions,
    const float* __restrict__ transitions,
    const int*   __restrict__ tags,
    const int*   __restrict__ mask,
    float*       __restrict__ out)
{
    __shared__ __align__(16) float sv[2][CC];
    __shared__ int s_last;
    const int lane = threadIdx.x;

    if (blockIdx.x < BB) {
        // ---------------- forward recursion (linear domain) ----------------
        const int b = blockIdx.x;

        // expT row for this lane (state i), packed into 16 f32x2 registers
        unsigned long long tp[16];
#pragma unroll
        for (int k = 0; k < 16; ++k) {
            float a = __expf(transitions[lane * CC + 2 * k]);
            float c = __expf(transitions[lane * CC + 2 * k + 1]);
            asm("mov.b64 %0, {%1, %2};" : "=l"(tp[k]) : "f"(a), "f"(c));
        }

        const float* em = emissions + (size_t)b * (LL * CC) + lane;

        // v = exp(alpha0), stored in sv[1]; step t reads sv[t&1]
        sv[1][lane] = __expf(em[0]);
        float Ml2 = 0.f;

        // 8-deep register prefetch of emission rows (coalesced 128B/warp/step)
        float ebuf[8];
#pragma unroll
        for (int k = 0; k < 8; ++k) ebuf[k] = em[(1 + k) * CC];
        const float* pf = em + (size_t)9 * CC;

        // main loop: t = 1 .. 2032 (254 x 8), prefetch rows 9 .. 2040 (no predicate)
#pragma unroll 1
        for (int blk = 0; blk < 254; ++blk) {
#pragma unroll
            for (int k = 0; k < 8; ++k) {
                float ev = ebuf[k];
                ebuf[k] = *pf;
                pf += CC;
                // t = blk*8 + 1 + k: parity (1+k)&1; renorm on odd t <=> (k&1)==0
                STEP((1 + k) & 1, ev, ((k & 1) == 0));
            }
        }

        // tail: t = 2033 .. 2047 (15 steps); ebuf has rows 2033..2040
        float ebuf2[7];
#pragma unroll
        for (int k = 0; k < 7; ++k) ebuf2[k] = em[(size_t)(2041 + k) * CC];
#pragma unroll
        for (int k = 0; k < 8; ++k) {    // t = 2033 + k  (odd at k even)
            STEP((1 + k) & 1, ebuf[k], ((k & 1) == 0));
        }
#pragma unroll
        for (int k = 0; k < 7; ++k) {    // t = 2041 + k  (odd at k even)
            STEP((1 + k) & 1, ebuf2[k], ((k & 1) == 0));
        }

        // log_Z = Ml2*ln2 + log(sum_i v_i); final v in sv[0] (t=2047 wrote sv[0])
        __syncthreads();
        float tot = sv[0][lane];
#pragma unroll
        for (int o = 16; o; o >>= 1) tot += __shfl_xor_sync(0xffffffffu, tot, o);
        if (lane == 0)
            g_logz[b] = (double)Ml2 * 0.6931471805599453 + log((double)tot);
    } else {
        // ---------------- path score ----------------
        const int b = blockIdx.x - BB;
        const int* tg = tags + (size_t)b * LL;
        const int* mk = mask + (size_t)b * LL;
        const float* eb = emissions + (size_t)b * (LL * CC);

        int ms = 0;
        for (int t = lane; t < LL; t += 32) ms += mk[t];
#pragma unroll
        for (int o = 16; o; o >>= 1) ms += __shfl_xor_sync(0xffffffffu, ms, o);

        double acc = 0.0;
        for (int t = lane; t < LL - 1; t += 32) {
            int a = tg[t], c = tg[t + 1];
            float m0 = (float)mk[t], m1 = (float)mk[t + 1];
            acc += (double)(eb[t * CC + a] * m0)
                 + (double)(transitions[a * CC + c] * m1);
        }
#pragma unroll
        for (int o = 16; o; o >>= 1) acc += __shfl_xor_sync(0xffffffffu, acc, o);

        if (lane == 0) {
            int last_idx = ms - 1; if (last_idx < 0) last_idx = 0;
            int msc = ms; if (msc < 1) msc = 1;
            int le_t = msc - 1;
            int last_tag = tg[last_idx];
            acc += (double)eb[le_t * CC + last_tag];
            g_score[b] = acc;
        }
    }

    // ---------------- fused finalize: last block reduces deterministically ----------
    if (lane == 0) {
        __threadfence();
        int old = atomicAdd(&g_ticket, 1);
        s_last = (old == 2 * BB - 1);
    }
    __syncthreads();
    if (s_last) {
        __threadfence();
        double acc = 0.0;
        for (int i = lane; i < BB; i += 32) acc += g_logz[i] - g_score[i];
#pragma unroll
        for (int o = 16; o; o >>= 1) acc += __shfl_xor_sync(0xffffffffu, acc, o);
        if (lane == 0) out[0] = (float)(acc / (double)BB);
    }
}

extern "C" void kernel_launch(void* const* d_in, const int* in_sizes, int n_in,
                              void* d_out, int out_size) {
    const float* emissions   = (const float*)d_in[0];
    const float* transitions = (const float*)d_in[1];
    const int*   tags        = (const int*)d_in[2];
    const int*   mask        = (const int*)d_in[3];
    (void)in_sizes; (void)n_in; (void)out_size;

    crf_init<<<1, 32>>>();
    crf_main<<<2 * BB, CC>>>(emissions, transitions, tags, mask, (float*)d_out);
}

// round 4
// speedup vs baseline: 1.3895x; 1.1277x over previous
#include <cuda_runtime.h>
#include <cstdint>

#define BB 512
#define LL 2048
#define CC 32

// Device scratch (no allocation allowed)
__device__ double g_logz[BB];
__device__ double g_score[BB];
__device__ int    g_ticket;

// ---------- packed f32x2 helpers (sm_103a; ptxas never emits FFMA2 from C++) ----------
__device__ __forceinline__ unsigned long long mul2(unsigned long long a, unsigned long long b) {
    unsigned long long r;
    asm("mul.rn.f32x2 %0, %1, %2;" : "=l"(r) : "l"(a), "l"(b));
    return r;
}
__device__ __forceinline__ void fma2(unsigned long long& c, unsigned long long a, unsigned long long b) {
    asm("fma.rn.f32x2 %0, %1, %2, %0;" : "+l"(c) : "l"(a), "l"(b));
}
__device__ __forceinline__ unsigned long long add2(unsigned long long a, unsigned long long b) {
    unsigned long long r;
    asm("add.rn.f32x2 %0, %1, %2;" : "=l"(r) : "l"(a), "l"(b));
    return r;
}
__device__ __forceinline__ float rcp_approx(float x) {
    float r; asm("rcp.approx.f32 %0, %1;" : "=f"(r) : "f"(x)); return r;
}

// One recursion step core. Reads sv[PAR_], writes sv[PAR_^1].
// EE_ (= exp(emit)*optional rcp(v0_prev)) is fully precomputed -> off critical path.
// 8 accumulators, depth-2 FMA cascade, 3-level packed add tree.
#define CORE(PAR_, EE_) do {                                                  \
    __syncwarp();                                                             \
    const ulonglong2* pv_ = (const ulonglong2*)(sv[(PAR_)]);                  \
    ulonglong2 q0_ = pv_[0], q1_ = pv_[1], q2_ = pv_[2], q3_ = pv_[3];        \
    ulonglong2 q4_ = pv_[4], q5_ = pv_[5], q6_ = pv_[6], q7_ = pv_[7];        \
    unsigned long long c0_ = mul2(q0_.x, tp[0]);                              \
    unsigned long long c1_ = mul2(q0_.y, tp[1]);                              \
    unsigned long long c2_ = mul2(q1_.x, tp[2]);                              \
    unsigned long long c3_ = mul2(q1_.y, tp[3]);                              \
    unsigned long long c4_ = mul2(q2_.x, tp[4]);                              \
    unsigned long long c5_ = mul2(q2_.y, tp[5]);                              \
    unsigned long long c6_ = mul2(q3_.x, tp[6]);                              \
    unsigned long long c7_ = mul2(q3_.y, tp[7]);                              \
    fma2(c0_, q4_.x, tp[8]);   fma2(c1_, q4_.y, tp[9]);                       \
    fma2(c2_, q5_.x, tp[10]);  fma2(c3_, q5_.y, tp[11]);                      \
    fma2(c4_, q6_.x, tp[12]);  fma2(c5_, q6_.y, tp[13]);                      \
    fma2(c6_, q7_.x, tp[14]);  fma2(c7_, q7_.y, tp[15]);                      \
    unsigned long long b0_ = add2(c0_, c1_);                                  \
    unsigned long long b1_ = add2(c2_, c3_);                                  \
    unsigned long long b2_ = add2(c4_, c5_);                                  \
    unsigned long long b3_ = add2(c6_, c7_);                                  \
    unsigned long long d0_ = add2(b0_, b1_);                                  \
    unsigned long long d1_ = add2(b2_, b3_);                                  \
    unsigned long long s__ = add2(d0_, d1_);                                  \
    float sl_, sh_;                                                           \
    asm("mov.b64 {%0, %1}, %2;" : "=f"(sl_), "=f"(sh_) : "l"(s__));           \
    vn = (sl_ + sh_) * (EE_);                                                 \
    sv[(PAR_) ^ 1][lane] = vn;                                                \
} while (0)

// After the step for time t, prepare ee for step t+1.
// Renorm happens on odd t (every 2 steps): rcp(v0) + log2 bookkeeping,
// all computed in the shadow of the next step's sync/LDS window.
#define PREP_EE(EVN_, RENORM_NEXT_) do {                                      \
    if (RENORM_NEXT_) {                                                       \
        float v0b_ = __shfl_sync(0xffffffffu, vn, 0);                         \
        ee = __expf(EVN_) * rcp_approx(v0b_);                                 \
        Ml2 += __log2f(v0b_);                                                 \
    } else {                                                                  \
        ee = __expf(EVN_);                                                    \
    }                                                                         \
} while (0)

__global__ void crf_init() {
    if (threadIdx.x == 0) g_ticket = 0;
}

// Blocks 0..BB-1: forward recursion (1 warp = 1 batch, lane = state).
// Blocks BB..2*BB-1: path score. Last finished block reduces (fixed order).
__global__ void __launch_bounds__(CC) crf_main(
    const float* __restrict__ emissions,
    const float* __restrict__ transitions,
    const int*   __restrict__ tags,
    const int*   __restrict__ mask,
    float*       __restrict__ out)
{
    __shared__ __align__(16) float sv[2][CC];
    const int lane = threadIdx.x;

    if (blockIdx.x < BB) {
        // ---------------- forward recursion (linear domain) ----------------
        const int b = blockIdx.x;

        // expT row for this lane (state i), packed into 16 f32x2 registers
        unsigned long long tp[16];
#pragma unroll
        for (int k = 0; k < 16; ++k) {
            float a = __expf(transitions[lane * CC + 2 * k]);
            float c = __expf(transitions[lane * CC + 2 * k + 1]);
            asm("mov.b64 %0, {%1, %2};" : "=l"(tp[k]) : "f"(a), "f"(c));
        }

        const float* em = emissions + (size_t)b * (LL * CC) + lane;

        // 8-deep register prefetch of emission rows (coalesced 128B/warp/step)
        float ebuf[8];
#pragma unroll
        for (int k = 0; k < 8; ++k) ebuf[k] = em[(1 + k) * CC];
        const float* pf = em + (size_t)9 * CC;

        // s_0 = exp(alpha0); step t reads sv[t&1]
        float vn = __expf(em[0]);
        sv[1][lane] = vn;
        float Ml2;
        float ee;
        {   // prepare ee for t=1 (renorm step): v0 of s_0 via shfl
            float v0b = __shfl_sync(0xffffffffu, vn, 0);
            ee  = __expf(ebuf[0]) * rcp_approx(v0b);
            Ml2 = __log2f(v0b);
        }

        // main loop: t = 1 .. 2032 (254 x 8); prefetch rows 9 .. 2040
#pragma unroll 1
        for (int blk = 0; blk < 254; ++blk) {
#pragma unroll
            for (int k = 0; k < 8; ++k) {
                ebuf[k] = *pf;           // refill (consumed via ee 8 steps later)
                pf += CC;
                CORE((1 + k) & 1, ee);   // t = 8*blk + 1 + k; parity = (1+k)&1
                // next step t+1 renorms iff t+1 odd <=> k odd
                PREP_EE(ebuf[(k + 1) & 7], (k & 1) == 1);
            }
        }

        // tail: t = 2033 .. 2047 (15 steps); ebuf holds rows 2033..2040
        float ebuf2[7];
#pragma unroll
        for (int k = 0; k < 7; ++k) ebuf2[k] = em[(size_t)(2041 + k) * CC];
#pragma unroll
        for (int k = 0; k < 8; ++k) {    // t = 2033 + k
            CORE((1 + k) & 1, ee);
            if (k < 7) PREP_EE(ebuf[k + 1], (k & 1) == 1);
            else       PREP_EE(ebuf2[0],   (k & 1) == 1);
        }
#pragma unroll
        for (int k = 0; k < 7; ++k) {    // t = 2041 + k
            CORE((1 + k) & 1, ee);
            if (k < 6) PREP_EE(ebuf2[k + 1], (k & 1) == 1);
        }

        // log_Z = Ml2*ln2 + log(sum_i v_i); t=2047 wrote sv[0]
        __syncwarp();
        float tot = sv[0][lane];
#pragma unroll
        for (int o = 16; o; o >>= 1) tot += __shfl_xor_sync(0xffffffffu, tot, o);
        if (lane == 0)
            g_logz[b] = (double)Ml2 * 0.6931471805599453 + log((double)tot);
    } else {
        // ---------------- path score ----------------
        const int b = blockIdx.x - BB;
        const int* tg = tags + (size_t)b * LL;
        const int* mk = mask + (size_t)b * LL;
        const float* eb = emissions + (size_t)b * (LL * CC);

        int ms = 0;
        for (int t = lane; t < LL; t += 32) ms += mk[t];
#pragma unroll
        for (int o = 16; o; o >>= 1) ms += __shfl_xor_sync(0xffffffffu, ms, o);

        double acc = 0.0;
        for (int t = lane; t < LL - 1; t += 32) {
            int a = tg[t], c = tg[t + 1];
            float m0 = (float)mk[t], m1 = (float)mk[t + 1];
            acc += (double)(eb[t * CC + a] * m0)
                 + (double)(transitions[a * CC + c] * m1);
        }
#pragma unroll
        for (int o = 16; o; o >>= 1) acc += __shfl_xor_sync(0xffffffffu, acc, o);

        if (lane == 0) {
            int last_idx = ms - 1; if (last_idx < 0) last_idx = 0;
            int msc = ms; if (msc < 1) msc = 1;
            int le_t = msc - 1;
            int last_tag = tg[last_idx];
            acc += (double)eb[le_t * CC + last_tag];
            g_score[b] = acc;
        }
    }

    // ---------------- fused finalize: last block reduces deterministically ---------
    int is_last = 0;
    if (lane == 0) {
        __threadfence();
        int old = atomicAdd(&g_ticket, 1);
        is_last = (old == 2 * BB - 1);
    }
    is_last = __shfl_sync(0xffffffffu, is_last, 0);
    if (is_last) {
        __threadfence();
        double acc = 0.0;
        for (int i = lane; i < BB; i += 32) acc += g_logz[i] - g_score[i];
#pragma unroll
        for (int o = 16; o; o >>= 1) acc += __shfl_xor_sync(0xffffffffu, acc, o);
        if (lane == 0) out[0] = (float)(acc / (double)BB);
    }
}

extern "C" void kernel_launch(void* const* d_in, const int* in_sizes, int n_in,
                              void* d_out, int out_size) {
    const float* emissions   = (const float*)d_in[0];
    const float* transitions = (const float*)d_in[1];
    const int*   tags        = (const int*)d_in[2];
    const int*   mask        = (const int*)d_in[3];
    (void)in_sizes; (void)n_in; (void)out_size;

    crf_init<<<1, 32>>>();
    crf_main<<<2 * BB, CC>>>(emissions, transitions, tags, mask, (float*)d_out);
}